// round 3
// baseline (speedup 1.0000x reference)
#include <cuda_runtime.h>
#include <float.h>
#include <math.h>

#define BSZ 4
#define ND 2048
#define NC 8192
#define DM 11
#define DMODEL 256
#define TOPK 32

// ---------------- scratch (no allocations allowed) ----------------
__device__ float g_xmicro[BSZ * ND * DMODEL];           // 8 MB
__device__ float g_Q[BSZ * ND * DMODEL];                // 8 MB
__device__ float g_Kf[BSZ * NC * DMODEL];               // 32 MB
__device__ float g_Vf[BSZ * NC * DMODEL];               // 32 MB
__device__ float g_scores[(size_t)BSZ * ND * NC];       // 268 MB
__device__ float g_attn[BSZ * ND * TOPK];
__device__ int   g_idx[BSZ * ND * TOPK];

// ---------------- kernel 0: x_micro = (micro @ mp_w) + b ; Q = x_micro @ wq --
// NOTE: bias added AFTER the k-sum, matching XLA's gemm-then-bias fusion.
// All accumulations: single fp32 accumulator, ascending k (cuBLAS SGEMM order).
__global__ __launch_bounds__(256) void k_proj_q(
    const float* __restrict__ micro, const float* __restrict__ mp_w,
    const float* __restrict__ mp_b, const float* __restrict__ wq)
{
    const int RB = 32;
    __shared__ float s_micro[RB][DM];
    __shared__ float s_mpw[DM][DMODEL];
    __shared__ float s_x[RB][DMODEL];
    const int t = threadIdx.x;
    const int row0 = blockIdx.x * RB;

    for (int i = t; i < RB * DM; i += 256)
        s_micro[i / DM][i % DM] = micro[(size_t)row0 * DM + i];
    for (int i = t; i < DM * DMODEL; i += 256)
        s_mpw[i / DMODEL][i % DMODEL] = mp_w[i];
    __syncthreads();

    const float bias = mp_b[t];
    for (int r = 0; r < RB; r++) {
        float acc = 0.f;
#pragma unroll
        for (int i = 0; i < DM; i++)
            acc = fmaf(s_micro[r][i], s_mpw[i][t], acc);
        acc = acc + bias;  // bias AFTER the sum (XLA fusion order)
        s_x[r][t] = acc;
        g_xmicro[(size_t)(row0 + r) * DMODEL + t] = acc;
    }
    __syncthreads();

    float q[RB];
#pragma unroll
    for (int r = 0; r < RB; r++) q[r] = 0.f;
    for (int d = 0; d < DMODEL; d += 2) {
        const float w0 = wq[(size_t)d * DMODEL + t];
        const float w1 = wq[(size_t)(d + 1) * DMODEL + t];
#pragma unroll
        for (int r = 0; r < RB; r++) {
            float2 x2 = *(const float2*)&s_x[r][d];
            q[r] = fmaf(x2.y, w1, fmaf(x2.x, w0, q[r]));  // ascending k
        }
    }
    for (int r = 0; r < RB; r++)
        g_Q[(size_t)(row0 + r) * DMODEL + t] = q[r];
}

// ---------------- kernel 1: K_full = macro@wk, V_full = macro@wv --------------
__global__ __launch_bounds__(256) void k_proj_kv(
    const float* __restrict__ macro, const float* __restrict__ wk,
    const float* __restrict__ wv)
{
    const int RB = 32;
    __shared__ float s_x[RB][DMODEL];  // 32 KB
    const int t = threadIdx.x;
    const int row0 = blockIdx.x * RB;

    for (int r = 0; r < RB; r++)
        s_x[r][t] = macro[(size_t)(row0 + r) * DMODEL + t];
    __syncthreads();

    float ka[RB], va[RB];
#pragma unroll
    for (int r = 0; r < RB; r++) { ka[r] = 0.f; va[r] = 0.f; }

    for (int d = 0; d < DMODEL; d += 2) {
        const float k0 = wk[(size_t)d * DMODEL + t];
        const float k1 = wk[(size_t)(d + 1) * DMODEL + t];
        const float v0 = wv[(size_t)d * DMODEL + t];
        const float v1 = wv[(size_t)(d + 1) * DMODEL + t];
#pragma unroll
        for (int r = 0; r < RB; r++) {
            float2 x2 = *(const float2*)&s_x[r][d];
            ka[r] = fmaf(x2.y, k1, fmaf(x2.x, k0, ka[r]));  // ascending k
            va[r] = fmaf(x2.y, v1, fmaf(x2.x, v0, va[r]));
        }
    }
    for (int r = 0; r < RB; r++) {
        g_Kf[(size_t)(row0 + r) * DMODEL + t] = ka[r];
        g_Vf[(size_t)(row0 + r) * DMODEL + t] = va[r];
    }
}

// ---------------- kernel 2: scores = (Q @ Kf^T) * 2^-4 ----------------------
// NT sgemm: C[n,m] = sum_d A[n,d]*B[m,d].  128x128 tile, BK=8, 8x8 microtile.
// Single accumulator per element, ascending k — mirrors cuBLAS SGEMM.
#define BM 128
#define BN 128
#define BK 8
__global__ __launch_bounds__(256) void k_scores()
{
    __shared__ float As[BK][BM];
    __shared__ float Bs[BK][BN];
    const int b = blockIdx.z;
    const float* __restrict__ A = g_Q + (size_t)b * ND * DMODEL;
    const float* __restrict__ Bm = g_Kf + (size_t)b * NC * DMODEL;
    float* __restrict__ C = g_scores + (size_t)b * ND * NC;

    const int n0 = blockIdx.y * BM;
    const int m0 = blockIdx.x * BN;
    const int tid = threadIdx.x;
    const int tx = tid & 15;   // -> m
    const int ty = tid >> 4;   // -> n
    const int lr = tid >> 1;       // 0..127 tile row for loads
    const int lk = (tid & 1) * 4;  // 0 or 4

    float acc[8][8];
#pragma unroll
    for (int i = 0; i < 8; i++)
#pragma unroll
        for (int j = 0; j < 8; j++) acc[i][j] = 0.f;

    for (int k0 = 0; k0 < DMODEL; k0 += BK) {
        float4 av = *(const float4*)(A + (size_t)(n0 + lr) * DMODEL + k0 + lk);
        float4 bv = *(const float4*)(Bm + (size_t)(m0 + lr) * DMODEL + k0 + lk);
        __syncthreads();
        As[lk + 0][lr] = av.x; As[lk + 1][lr] = av.y;
        As[lk + 2][lr] = av.z; As[lk + 3][lr] = av.w;
        Bs[lk + 0][lr] = bv.x; Bs[lk + 1][lr] = bv.y;
        Bs[lk + 2][lr] = bv.z; Bs[lk + 3][lr] = bv.w;
        __syncthreads();
#pragma unroll
        for (int kk = 0; kk < BK; kk++) {
            float4 a0 = *(const float4*)&As[kk][ty * 8];
            float4 a1 = *(const float4*)&As[kk][ty * 8 + 4];
            float4 b0 = *(const float4*)&Bs[kk][tx * 8];
            float4 b1 = *(const float4*)&Bs[kk][tx * 8 + 4];
            float a[8] = {a0.x, a0.y, a0.z, a0.w, a1.x, a1.y, a1.z, a1.w};
            float bb[8] = {b0.x, b0.y, b0.z, b0.w, b1.x, b1.y, b1.z, b1.w};
#pragma unroll
            for (int i = 0; i < 8; i++)
#pragma unroll
                for (int j = 0; j < 8; j++)
                    acc[i][j] = fmaf(a[i], bb[j], acc[i][j]);
        }
    }

    const float scale = 0.0625f;  // exact 2^-4
#pragma unroll
    for (int i = 0; i < 8; i++) {
        const size_t rowoff = (size_t)(n0 + ty * 8 + i) * NC + m0 + tx * 8;
        float4 o0, o1;
        o0.x = acc[i][0] * scale; o0.y = acc[i][1] * scale;
        o0.z = acc[i][2] * scale; o0.w = acc[i][3] * scale;
        o1.x = acc[i][4] * scale; o1.y = acc[i][5] * scale;
        o1.z = acc[i][6] * scale; o1.w = acc[i][7] * scale;
        *(float4*)(C + rowoff) = o0;
        *(float4*)(C + rowoff + 4) = o1;
    }
}

// ---------------- kernel 3: top-32 (desc, tie->lowest idx) + softmax ---------
__global__ __launch_bounds__(256) void k_topk(float* __restrict__ out_attn,
                                              float* __restrict__ out_idxf)
{
    const int q = blockIdx.x;  // 0..BSZ*ND-1
    const float* __restrict__ row = g_scores + (size_t)q * NC;
    const int t = threadIdx.x;
    const int lane = t & 31, warp = t >> 5;

    float v[32];
#pragma unroll
    for (int i = 0; i < 32; i++) v[i] = row[t + (i << 8)];

    __shared__ float s_val[8];
    __shared__ int s_idx[8];
    __shared__ float s_topv[TOPK];
    __shared__ int s_topi[TOPK];

    for (int it = 0; it < TOPK; it++) {
        float bv = -FLT_MAX;
        int bi = NC;
#pragma unroll
        for (int i = 0; i < 32; i++) {
            // indices ascend with i, so strictly-greater keeps lowest index
            if (v[i] > bv) { bv = v[i]; bi = t + (i << 8); }
        }
#pragma unroll
        for (int s = 16; s > 0; s >>= 1) {
            float ov = __shfl_down_sync(0xffffffffu, bv, s);
            int oi = __shfl_down_sync(0xffffffffu, bi, s);
            if (ov > bv || (ov == bv && oi < bi)) { bv = ov; bi = oi; }
        }
        if (lane == 0) { s_val[warp] = bv; s_idx[warp] = bi; }
        __syncthreads();
        if (t == 0) {
            float wv_ = s_val[0]; int wi_ = s_idx[0];
#pragma unroll
            for (int w = 1; w < 8; w++)
                if (s_val[w] > wv_ || (s_val[w] == wv_ && s_idx[w] < wi_)) {
                    wv_ = s_val[w]; wi_ = s_idx[w];
                }
            s_topv[it] = wv_; s_topi[it] = wi_;
        }
        __syncthreads();
        const int wi = s_topi[it];
#pragma unroll
        for (int i = 0; i < 32; i++)
            if (wi == t + (i << 8)) v[i] = -FLT_MAX;
    }
    __syncthreads();

    if (t < TOPK) {
        float val = s_topv[t];
        float m = val;
#pragma unroll
        for (int s = 16; s > 0; s >>= 1)
            m = fmaxf(m, __shfl_xor_sync(0xffffffffu, m, s));
        float e = expf(val - m);
        float sum = e;
#pragma unroll
        for (int s = 16; s > 0; s >>= 1)
            sum += __shfl_xor_sync(0xffffffffu, sum, s);
        float a = e / sum;
        out_attn[(size_t)q * TOPK + t] = a;
        out_idxf[(size_t)q * TOPK + t] = (float)s_topi[t];
        g_attn[(size_t)q * TOPK + t] = a;
        g_idx[(size_t)q * TOPK + t] = s_topi[t];
    }
}

// ---------------- kernel 4: context gather + out proj + residual -------------
__global__ __launch_bounds__(256) void k_final(const float* __restrict__ op_w,
                                               const float* __restrict__ op_b,
                                               float* __restrict__ out)
{
    const int QB = 8;
    __shared__ float s_attn[QB][TOPK];
    __shared__ int s_idx2[QB][TOPK];
    __shared__ float s_ctx[QB][DMODEL];  // 8 KB
    const int t = threadIdx.x;
    const int q0 = blockIdx.x * QB;
    const int b = q0 / ND;

    if (t < QB * TOPK) {
        s_attn[t / TOPK][t & 31] = g_attn[(size_t)q0 * TOPK + t];
        s_idx2[t / TOPK][t & 31] = g_idx[(size_t)q0 * TOPK + t];
    }
    __syncthreads();

    const float* __restrict__ V = g_Vf + (size_t)b * NC * DMODEL;
#pragma unroll
    for (int r = 0; r < QB; r++) {
        float c = 0.f;
#pragma unroll 8
        for (int k = 0; k < TOPK; k++)
            c = fmaf(s_attn[r][k], V[(size_t)s_idx2[r][k] * DMODEL + t], c);
        s_ctx[r][t] = c;
    }
    __syncthreads();

    float o[QB];
    const float bias = op_b[t];
#pragma unroll
    for (int r = 0; r < QB; r++) o[r] = 0.f;

    for (int d = 0; d < DMODEL; d += 2) {
        const float w0 = op_w[(size_t)d * DMODEL + t];
        const float w1 = op_w[(size_t)(d + 1) * DMODEL + t];
#pragma unroll
        for (int r = 0; r < QB; r++) {
            float2 c2 = *(const float2*)&s_ctx[r][d];
            o[r] = fmaf(c2.y, w1, fmaf(c2.x, w0, o[r]));
        }
    }
#pragma unroll
    for (int r = 0; r < QB; r++)
        out[(size_t)(q0 + r) * DMODEL + t] =
            g_xmicro[(size_t)(q0 + r) * DMODEL + t] + o[r] + bias;
}

// ---------------- launch -----------------------------------------------------
extern "C" void kernel_launch(void* const* d_in, const int* in_sizes, int n_in,
                              void* d_out, int out_size)
{
    const float* micro = (const float*)d_in[0];
    const float* macro = (const float*)d_in[1];
    const float* mp_w = (const float*)d_in[2];
    const float* mp_b = (const float*)d_in[3];
    const float* wq = (const float*)d_in[4];
    const float* wk = (const float*)d_in[5];
    const float* wv = (const float*)d_in[6];
    const float* op_w = (const float*)d_in[7];
    const float* op_b = (const float*)d_in[8];

    float* out = (float*)d_out;
    float* out_attn = out + (size_t)BSZ * ND * DMODEL;
    float* out_idxf = out_attn + (size_t)BSZ * ND * TOPK;

    k_proj_q<<<(BSZ * ND) / 32, 256>>>(micro, mp_w, mp_b, wq);
    k_proj_kv<<<(BSZ * NC) / 32, 256>>>(macro, wk, wv);
    dim3 g2(NC / BN, ND / BM, BSZ);
    k_scores<<<g2, 256>>>();
    k_topk<<<BSZ * ND, 256>>>(out_attn, out_idxf);
    k_final<<<(BSZ * ND) / 8, 256>>>(op_w, op_b, out);
}

// round 4
// speedup vs baseline: 1.4567x; 1.4567x over previous
#include <cuda_runtime.h>
#include <float.h>
#include <math.h>
#include <stdint.h>

#define BSZ 4
#define ND 2048
#define NC 8192
#define DM 11
#define DMODEL 256
#define TOPK 32

// ---------------- scratch (no allocations allowed) ----------------
__device__ float g_xmicro[BSZ * ND * DMODEL];           // 8 MB
__device__ float g_Q[BSZ * ND * DMODEL];                // 8 MB
__device__ float g_Kf[BSZ * NC * DMODEL];               // 32 MB
__device__ float g_Vf[BSZ * NC * DMODEL];               // 32 MB
__device__ float g_scores[(size_t)BSZ * ND * NC];       // 268 MB
__device__ float g_attn[BSZ * ND * TOPK];
__device__ int   g_idx[BSZ * ND * TOPK];

// ---------------- kernel 0: x_micro = (micro @ mp_w) + b ; Q = x_micro @ wq --
// Bias added AFTER the k-sum (XLA fusion order). Ascending-k fp32 chains.
__global__ __launch_bounds__(256) void k_proj_q(
    const float* __restrict__ micro, const float* __restrict__ mp_w,
    const float* __restrict__ mp_b, const float* __restrict__ wq)
{
    const int RB = 32;
    __shared__ float s_micro[RB][DM];
    __shared__ float s_mpw[DM][DMODEL];
    __shared__ float s_x[RB][DMODEL];
    const int t = threadIdx.x;
    const int row0 = blockIdx.x * RB;

    for (int i = t; i < RB * DM; i += 256)
        s_micro[i / DM][i % DM] = micro[(size_t)row0 * DM + i];
    for (int i = t; i < DM * DMODEL; i += 256)
        s_mpw[i / DMODEL][i % DMODEL] = mp_w[i];
    __syncthreads();

    const float bias = mp_b[t];
    for (int r = 0; r < RB; r++) {
        float acc = 0.f;
#pragma unroll
        for (int i = 0; i < DM; i++)
            acc = fmaf(s_micro[r][i], s_mpw[i][t], acc);
        acc = acc + bias;
        s_x[r][t] = acc;
        g_xmicro[(size_t)(row0 + r) * DMODEL + t] = acc;
    }
    __syncthreads();

    float q[RB];
#pragma unroll
    for (int r = 0; r < RB; r++) q[r] = 0.f;
    for (int d = 0; d < DMODEL; d += 2) {
        const float w0 = wq[(size_t)d * DMODEL + t];
        const float w1 = wq[(size_t)(d + 1) * DMODEL + t];
#pragma unroll
        for (int r = 0; r < RB; r++) {
            float2 x2 = *(const float2*)&s_x[r][d];
            q[r] = fmaf(x2.y, w1, fmaf(x2.x, w0, q[r]));
        }
    }
    for (int r = 0; r < RB; r++)
        g_Q[(size_t)(row0 + r) * DMODEL + t] = q[r];
}

// ---------------- kernel 1: K_full = macro@wk, V_full = macro@wv --------------
__global__ __launch_bounds__(256) void k_proj_kv(
    const float* __restrict__ macro, const float* __restrict__ wk,
    const float* __restrict__ wv)
{
    const int RB = 32;
    __shared__ float s_x[RB][DMODEL];
    const int t = threadIdx.x;
    const int row0 = blockIdx.x * RB;

    for (int r = 0; r < RB; r++)
        s_x[r][t] = macro[(size_t)(row0 + r) * DMODEL + t];
    __syncthreads();

    float ka[RB], va[RB];
#pragma unroll
    for (int r = 0; r < RB; r++) { ka[r] = 0.f; va[r] = 0.f; }

    for (int d = 0; d < DMODEL; d += 2) {
        const float k0 = wk[(size_t)d * DMODEL + t];
        const float k1 = wk[(size_t)(d + 1) * DMODEL + t];
        const float v0 = wv[(size_t)d * DMODEL + t];
        const float v1 = wv[(size_t)(d + 1) * DMODEL + t];
#pragma unroll
        for (int r = 0; r < RB; r++) {
            float2 x2 = *(const float2*)&s_x[r][d];
            ka[r] = fmaf(x2.y, k1, fmaf(x2.x, k0, ka[r]));
            va[r] = fmaf(x2.y, v1, fmaf(x2.x, v0, va[r]));
        }
    }
    for (int r = 0; r < RB; r++) {
        g_Kf[(size_t)(row0 + r) * DMODEL + t] = ka[r];
        g_Vf[(size_t)(row0 + r) * DMODEL + t] = va[r];
    }
}

// ---------------- kernel 2: scores = (Q @ Kf^T) * 2^-4 ----------------------
// Double-buffered smem; per-accumulator FMA order identical to round 3
// (single accumulator, ascending k) -> bit-identical output.
#define BM 128
#define BN 128
#define BK 8
__global__ __launch_bounds__(256) void k_scores()
{
    __shared__ float As[2][BK][BM];
    __shared__ float Bs[2][BK][BN];
    const int b = blockIdx.z;
    const float* __restrict__ A = g_Q + (size_t)b * ND * DMODEL;
    const float* __restrict__ Bm = g_Kf + (size_t)b * NC * DMODEL;
    float* __restrict__ C = g_scores + (size_t)b * ND * NC;

    const int n0 = blockIdx.y * BM;
    const int m0 = blockIdx.x * BN;
    const int tid = threadIdx.x;
    const int tx = tid & 15;
    const int ty = tid >> 4;
    const int lr = tid >> 1;
    const int lk = (tid & 1) * 4;

    const float* aptr = A + (size_t)(n0 + lr) * DMODEL + lk;
    const float* bptr = Bm + (size_t)(m0 + lr) * DMODEL + lk;

    float acc[8][8];
#pragma unroll
    for (int i = 0; i < 8; i++)
#pragma unroll
        for (int j = 0; j < 8; j++) acc[i][j] = 0.f;

    // prologue: tile 0 -> buf 0
    {
        float4 av = *(const float4*)(aptr);
        float4 bv = *(const float4*)(bptr);
        As[0][lk + 0][lr] = av.x; As[0][lk + 1][lr] = av.y;
        As[0][lk + 2][lr] = av.z; As[0][lk + 3][lr] = av.w;
        Bs[0][lk + 0][lr] = bv.x; Bs[0][lk + 1][lr] = bv.y;
        Bs[0][lk + 2][lr] = bv.z; Bs[0][lk + 3][lr] = bv.w;
    }
    __syncthreads();

    const int NT = DMODEL / BK;  // 32
    int cur = 0;
    for (int kt = 0; kt < NT; kt++) {
        float4 nav, nbv;
        if (kt + 1 < NT) {
            nav = *(const float4*)(aptr + (kt + 1) * BK);
            nbv = *(const float4*)(bptr + (kt + 1) * BK);
        }
#pragma unroll
        for (int kk = 0; kk < BK; kk++) {
            float4 a0 = *(const float4*)&As[cur][kk][ty * 8];
            float4 a1 = *(const float4*)&As[cur][kk][ty * 8 + 4];
            float4 b0 = *(const float4*)&Bs[cur][kk][tx * 8];
            float4 b1 = *(const float4*)&Bs[cur][kk][tx * 8 + 4];
            float a[8] = {a0.x, a0.y, a0.z, a0.w, a1.x, a1.y, a1.z, a1.w};
            float bb[8] = {b0.x, b0.y, b0.z, b0.w, b1.x, b1.y, b1.z, b1.w};
#pragma unroll
            for (int i = 0; i < 8; i++)
#pragma unroll
                for (int j = 0; j < 8; j++)
                    acc[i][j] = fmaf(a[i], bb[j], acc[i][j]);
        }
        __syncthreads();
        if (kt + 1 < NT) {
            const int nxt = cur ^ 1;
            As[nxt][lk + 0][lr] = nav.x; As[nxt][lk + 1][lr] = nav.y;
            As[nxt][lk + 2][lr] = nav.z; As[nxt][lk + 3][lr] = nav.w;
            Bs[nxt][lk + 0][lr] = nbv.x; Bs[nxt][lk + 1][lr] = nbv.y;
            Bs[nxt][lk + 2][lr] = nbv.z; Bs[nxt][lk + 3][lr] = nbv.w;
            __syncthreads();
            cur = nxt;
        }
    }

    const float scale = 0.0625f;
#pragma unroll
    for (int i = 0; i < 8; i++) {
        const size_t rowoff = (size_t)(n0 + ty * 8 + i) * NC + m0 + tx * 8;
        float4 o0, o1;
        o0.x = acc[i][0] * scale; o0.y = acc[i][1] * scale;
        o0.z = acc[i][2] * scale; o0.w = acc[i][3] * scale;
        o1.x = acc[i][4] * scale; o1.y = acc[i][5] * scale;
        o1.z = acc[i][6] * scale; o1.w = acc[i][7] * scale;
        *(float4*)(C + rowoff) = o0;
        *(float4*)(C + rowoff + 4) = o1;
    }
}

// ---------------- kernel 3: radix-select top-32 + softmax --------------------
// Exact selection over unchanged fp32 scores; tie -> lowest index.
__device__ __forceinline__ uint32_t fkey(float v) {
    uint32_t u = __float_as_uint(v);
    return (u & 0x80000000u) ? ~u : (u | 0x80000000u);
}
__device__ __forceinline__ float inv_key(uint32_t u) {
    return __uint_as_float((u & 0x80000000u) ? (u & 0x7FFFFFFFu) : ~u);
}
// warp-aggregated histogram add (converged full-warp call sites)
__device__ __forceinline__ void hist_add_full(int b, int* hist) {
    unsigned m = __match_any_sync(0xffffffffu, b);
    if ((threadIdx.x & 31) == (__ffs(m) - 1)) atomicAdd(&hist[b], __popc(m));
}

__global__ __launch_bounds__(256) void k_topk(float* __restrict__ out_attn,
                                              float* __restrict__ out_idxf)
{
    const int q = blockIdx.x;
    const float* __restrict__ row = g_scores + (size_t)q * NC;
    const int t = threadIdx.x;
    const int lane = t & 31, warp = t >> 5;

    __shared__ uint32_t s_keys[NC];    // 32 KB
    __shared__ int s_hist[256];
    __shared__ int s_S[257];
    __shared__ int s_info[4];          // [0]=byte B, [1]=S[B+1], [2]=tie idx
    __shared__ float s_candv[TOPK];
    __shared__ int   s_candi[TOPK];
    __shared__ int   s_cnt;
    __shared__ int   s_redi[8];
    __shared__ float s_topv[TOPK];
    __shared__ int   s_topi[TOPK];

    if (t < 256) s_hist[t] = 0;
    if (t == 0) { s_S[256] = 0; s_cnt = 0; }
    __syncthreads();

    // ---- pass 0: load + transform + top-byte histogram ----
#pragma unroll
    for (int i = 0; i < 8; i++) {
        const int base = i * 1024 + (t << 2);
        float4 v4 = *(const float4*)(row + base);
        uint32_t u0 = fkey(v4.x), u1 = fkey(v4.y);
        uint32_t u2 = fkey(v4.z), u3 = fkey(v4.w);
        uint4 pk; pk.x = u0; pk.y = u1; pk.z = u2; pk.w = u3;
        *(uint4*)&s_keys[base] = pk;
        hist_add_full(u0 >> 24, s_hist);
        hist_add_full(u1 >> 24, s_hist);
        hist_add_full(u2 >> 24, s_hist);
        hist_add_full(u3 >> 24, s_hist);
    }

    int need = TOPK;
    uint32_t pref = 0;

    for (int p = 0; p < 4; p++) {
        __syncthreads();
        // suffix scan over 256 bins (warp 0)
        if (warp == 0) {
            const int base = lane * 8;
            int c[8];
#pragma unroll
            for (int k2 = 0; k2 < 8; k2++) c[k2] = s_hist[base + k2];
            int sum = 0;
#pragma unroll
            for (int k2 = 7; k2 >= 0; k2--) { sum += c[k2]; c[k2] = sum; }
            int v = sum;
#pragma unroll
            for (int off = 1; off < 32; off <<= 1) {
                int o = __shfl_down_sync(0xffffffffu, v, off);
                if (lane + off < 32) v += o;
            }
            const int run = v - sum;
#pragma unroll
            for (int k2 = 0; k2 < 8; k2++) s_S[base + k2] = c[k2] + run;
        }
        __syncthreads();
        if (t < 256) {
            if (s_S[t] >= need && s_S[t + 1] < need) {
                s_info[0] = t;
                s_info[1] = s_S[t + 1];
            }
        }
        __syncthreads();
        const int B = s_info[0];
        need -= s_info[1];
        pref = (pref << 8) | (uint32_t)B;

        if (p < 3) {
            // next pass histogram
            if (t < 256) s_hist[t] = 0;
            __syncthreads();
            const int shift = 24 - 8 * (p + 1);
            for (int i = 0; i < 32; i++) {
                const uint32_t u = s_keys[i * 256 + t];
                if ((u >> (shift + 8)) == pref)
                    atomicAdd(&s_hist[(u >> shift) & 255], 1);
            }
        }
    }
    __syncthreads();

    const uint32_t T = pref;       // exact key of the 32nd element
    // ---- collect strictly-greater candidates (count = TOPK - need <= 31) ----
    for (int i = 0; i < 32; i++) {
        const int idx = i * 256 + t;
        const uint32_t u = s_keys[idx];
        if (u > T) {
            const int pos = atomicAdd(&s_cnt, 1);
            s_candv[pos] = inv_key(u);
            s_candi[pos] = idx;
        }
    }
    __syncthreads();
    const int cab = s_cnt;         // == TOPK - need
    const int r = TOPK - cab;      // ties to take (>= 1), lowest indices first

    // ---- ties: r smallest indices with key == T ----
    int prev = -1;
    for (int j = 0; j < r; j++) {
        int mymin = 0x7fffffff;
        for (int i = 0; i < 32; i++) {
            const int idx = i * 256 + t;
            if (idx > prev && s_keys[idx] == T) { mymin = idx; break; }
        }
#pragma unroll
        for (int off = 16; off > 0; off >>= 1)
            mymin = min(mymin, __shfl_down_sync(0xffffffffu, mymin, off));
        if (lane == 0) s_redi[warp] = mymin;
        __syncthreads();
        if (t == 0) {
            int mn = s_redi[0];
#pragma unroll
            for (int w = 1; w < 8; w++) mn = min(mn, s_redi[w]);
            s_candi[cab + j] = mn;
            s_candv[cab + j] = inv_key(T);
            s_info[2] = mn;
        }
        __syncthreads();
        prev = s_info[2];
    }

    // ---- rank-sort the 32 candidates by (value desc, index asc) ----
    if (t < TOPK) {
        const float mv = s_candv[t];
        const int mi = s_candi[t];
        int rank = 0;
#pragma unroll
        for (int j = 0; j < TOPK; j++) {
            const float ov = s_candv[j];
            const int oi = s_candi[j];
            rank += (ov > mv) || (ov == mv && oi < mi);
        }
        s_topv[rank] = mv;
        s_topi[rank] = mi;
    }
    __syncthreads();

    // ---- softmax + outputs (warp 0) ----
    if (warp == 0) {
        const float val = s_topv[lane];
        float m = val;
#pragma unroll
        for (int s = 16; s > 0; s >>= 1)
            m = fmaxf(m, __shfl_xor_sync(0xffffffffu, m, s));
        const float e = expf(val - m);
        float sum = e;
#pragma unroll
        for (int s = 16; s > 0; s >>= 1)
            sum += __shfl_xor_sync(0xffffffffu, sum, s);
        const float a = e / sum;
        out_attn[(size_t)q * TOPK + lane] = a;
        out_idxf[(size_t)q * TOPK + lane] = (float)s_topi[lane];
        g_attn[(size_t)q * TOPK + lane] = a;
        g_idx[(size_t)q * TOPK + lane] = s_topi[lane];
    }
}

// ---------------- kernel 4: context gather + out proj + residual -------------
__global__ __launch_bounds__(256) void k_final(const float* __restrict__ op_w,
                                               const float* __restrict__ op_b,
                                               float* __restrict__ out)
{
    const int QB = 8;
    __shared__ float s_attn[QB][TOPK];
    __shared__ int s_idx2[QB][TOPK];
    __shared__ float s_ctx[QB][DMODEL];
    const int t = threadIdx.x;
    const int q0 = blockIdx.x * QB;
    const int b = q0 / ND;

    if (t < QB * TOPK) {
        s_attn[t / TOPK][t & 31] = g_attn[(size_t)q0 * TOPK + t];
        s_idx2[t / TOPK][t & 31] = g_idx[(size_t)q0 * TOPK + t];
    }
    __syncthreads();

    const float* __restrict__ V = g_Vf + (size_t)b * NC * DMODEL;
#pragma unroll
    for (int r = 0; r < QB; r++) {
        float c = 0.f;
#pragma unroll 8
        for (int k = 0; k < TOPK; k++)
            c = fmaf(s_attn[r][k], V[(size_t)s_idx2[r][k] * DMODEL + t], c);
        s_ctx[r][t] = c;
    }
    __syncthreads();

    float o[QB];
    const float bias = op_b[t];
#pragma unroll
    for (int r = 0; r < QB; r++) o[r] = 0.f;

    for (int d = 0; d < DMODEL; d += 2) {
        const float w0 = op_w[(size_t)d * DMODEL + t];
        const float w1 = op_w[(size_t)(d + 1) * DMODEL + t];
#pragma unroll
        for (int r = 0; r < QB; r++) {
            float2 c2 = *(const float2*)&s_ctx[r][d];
            o[r] = fmaf(c2.y, w1, fmaf(c2.x, w0, o[r]));
        }
    }
#pragma unroll
    for (int r = 0; r < QB; r++)
        out[(size_t)(q0 + r) * DMODEL + t] =
            g_xmicro[(size_t)(q0 + r) * DMODEL + t] + o[r] + bias;
}

// ---------------- launch -----------------------------------------------------
extern "C" void kernel_launch(void* const* d_in, const int* in_sizes, int n_in,
                              void* d_out, int out_size)
{
    const float* micro = (const float*)d_in[0];
    const float* macro = (const float*)d_in[1];
    const float* mp_w = (const float*)d_in[2];
    const float* mp_b = (const float*)d_in[3];
    const float* wq = (const float*)d_in[4];
    const float* wk = (const float*)d_in[5];
    const float* wv = (const float*)d_in[6];
    const float* op_w = (const float*)d_in[7];
    const float* op_b = (const float*)d_in[8];

    float* out = (float*)d_out;
    float* out_attn = out + (size_t)BSZ * ND * DMODEL;
    float* out_idxf = out_attn + (size_t)BSZ * ND * TOPK;

    k_proj_q<<<(BSZ * ND) / 32, 256>>>(micro, mp_w, mp_b, wq);
    k_proj_kv<<<(BSZ * NC) / 32, 256>>>(macro, wk, wv);
    dim3 g2(NC / BN, ND / BM, BSZ);
    k_scores<<<g2, 256>>>();
    k_topk<<<BSZ * ND, 256>>>(out_attn, out_idxf);
    k_final<<<(BSZ * ND) / 8, 256>>>(op_w, op_b, out);
}

// round 5
// speedup vs baseline: 1.5382x; 1.0559x over previous
#include <cuda_runtime.h>
#include <float.h>
#include <math.h>
#include <stdint.h>

#define BSZ 4
#define ND 2048
#define NC 8192
#define DM 11
#define DMODEL 256
#define TOPK 32

// ---------------- scratch (no allocations allowed) ----------------
__device__ float g_xmicro[BSZ * ND * DMODEL];           // 8 MB
__device__ float g_Q[BSZ * ND * DMODEL];                // 8 MB
__device__ float g_Kf[BSZ * NC * DMODEL];               // 32 MB
__device__ float g_Vf[BSZ * NC * DMODEL];               // 32 MB
__device__ float g_scores[(size_t)BSZ * ND * NC];       // 268 MB
__device__ float g_attn[BSZ * ND * TOPK];
__device__ int   g_idx[BSZ * ND * TOPK];

// ---------------- packed f32x2 helpers (Blackwell 2x fp32) -------------------
// Each lane of fma.rn.f32x2 is an independent IEEE rn FMA == scalar fmaf.
__device__ __forceinline__ uint64_t pack2(float lo, float hi) {
    uint64_t d;
    asm("mov.b64 %0, {%1, %2};" : "=l"(d) : "f"(lo), "f"(hi));
    return d;
}
__device__ __forceinline__ void unpack2(uint64_t v, float& lo, float& hi) {
    asm("mov.b64 {%0, %1}, %2;" : "=f"(lo), "=f"(hi) : "l"(v));
}
__device__ __forceinline__ uint64_t ffma2(uint64_t a, uint64_t b, uint64_t c) {
    uint64_t d;
    asm("fma.rn.f32x2 %0, %1, %2, %3;" : "=l"(d) : "l"(a), "l"(b), "l"(c));
    return d;
}

// ---------------- kernel 0: x_micro = (micro @ mp_w) + b ; Q = x_micro @ wq --
// Bias added AFTER the k-sum (XLA fusion order). Ascending-k fp32 chains.
__global__ __launch_bounds__(256) void k_proj_q(
    const float* __restrict__ micro, const float* __restrict__ mp_w,
    const float* __restrict__ mp_b, const float* __restrict__ wq)
{
    const int RB = 32;
    __shared__ float s_micro[RB][DM];
    __shared__ float s_mpw[DM][DMODEL];
    __shared__ float s_x[RB][DMODEL];
    const int t = threadIdx.x;
    const int row0 = blockIdx.x * RB;

    for (int i = t; i < RB * DM; i += 256)
        s_micro[i / DM][i % DM] = micro[(size_t)row0 * DM + i];
    for (int i = t; i < DM * DMODEL; i += 256)
        s_mpw[i / DMODEL][i % DMODEL] = mp_w[i];
    __syncthreads();

    const float bias = mp_b[t];
    for (int r = 0; r < RB; r++) {
        float acc = 0.f;
#pragma unroll
        for (int i = 0; i < DM; i++)
            acc = fmaf(s_micro[r][i], s_mpw[i][t], acc);
        acc = acc + bias;
        s_x[r][t] = acc;
        g_xmicro[(size_t)(row0 + r) * DMODEL + t] = acc;
    }
    __syncthreads();

    float q[RB];
#pragma unroll
    for (int r = 0; r < RB; r++) q[r] = 0.f;
    for (int d = 0; d < DMODEL; d += 2) {
        const float w0 = wq[(size_t)d * DMODEL + t];
        const float w1 = wq[(size_t)(d + 1) * DMODEL + t];
#pragma unroll
        for (int r = 0; r < RB; r++) {
            float2 x2 = *(const float2*)&s_x[r][d];
            q[r] = fmaf(x2.y, w1, fmaf(x2.x, w0, q[r]));
        }
    }
    for (int r = 0; r < RB; r++)
        g_Q[(size_t)(row0 + r) * DMODEL + t] = q[r];
}

// ---------------- kernel 1: K_full, V_full via packed f32x2 ------------------
// Accumulators packed across adjacent macro-row pairs; x-pairs come free from
// a transposed smem layout via 64-bit broadcast loads. Per-accumulator chain:
// single fp32 lane, ascending d -> bit-identical to round 4.
__global__ __launch_bounds__(256) void k_proj_kv(
    const float* __restrict__ macro, const float* __restrict__ wk,
    const float* __restrict__ wv)
{
    const int RB = 32;
    __shared__ float s_x[DMODEL][RB + 2];  // transposed, pad keeps b64 align
    const int t = threadIdx.x;
    const int row0 = blockIdx.x * RB;

#pragma unroll 4
    for (int r = 0; r < RB; r++)
        s_x[t][r] = macro[(size_t)(row0 + r) * DMODEL + t];
    __syncthreads();

    uint64_t ka2[RB / 2], va2[RB / 2];
#pragma unroll
    for (int p = 0; p < RB / 2; p++) { ka2[p] = 0ull; va2[p] = 0ull; }

    for (int d = 0; d < DMODEL; d++) {
        const float kw = wk[(size_t)d * DMODEL + t];
        const float vw = wv[(size_t)d * DMODEL + t];
        const uint64_t kw2 = pack2(kw, kw);
        const uint64_t vw2 = pack2(vw, vw);
#pragma unroll
        for (int p = 0; p < RB / 2; p++) {
            const uint64_t x2 = *(const uint64_t*)&s_x[d][2 * p];
            ka2[p] = ffma2(x2, kw2, ka2[p]);
            va2[p] = ffma2(x2, vw2, va2[p]);
        }
    }
#pragma unroll
    for (int p = 0; p < RB / 2; p++) {
        float k0, k1, v0, v1;
        unpack2(ka2[p], k0, k1);
        unpack2(va2[p], v0, v1);
        g_Kf[(size_t)(row0 + 2 * p) * DMODEL + t] = k0;
        g_Kf[(size_t)(row0 + 2 * p + 1) * DMODEL + t] = k1;
        g_Vf[(size_t)(row0 + 2 * p) * DMODEL + t] = v0;
        g_Vf[(size_t)(row0 + 2 * p + 1) * DMODEL + t] = v1;
    }
}

// ---------------- kernel 2: scores = (Q @ Kf^T) * 2^-4 ----------------------
// Double-buffered smem + packed f32x2 FMAs. Accumulators packed across
// adjacent j columns (b-pairs adjacent in smem -> free 64-bit loads).
// Each lane chain: single accumulator, ascending k -> bit-identical output.
#define BM 128
#define BN 128
#define BK 8
__global__ __launch_bounds__(256) void k_scores()
{
    __shared__ float As[2][BK][BM];
    __shared__ float Bs[2][BK][BN];
    const int b = blockIdx.z;
    const float* __restrict__ A = g_Q + (size_t)b * ND * DMODEL;
    const float* __restrict__ Bm = g_Kf + (size_t)b * NC * DMODEL;
    float* __restrict__ C = g_scores + (size_t)b * ND * NC;

    const int n0 = blockIdx.y * BM;
    const int m0 = blockIdx.x * BN;
    const int tid = threadIdx.x;
    const int tx = tid & 15;
    const int ty = tid >> 4;
    const int lr = tid >> 1;
    const int lk = (tid & 1) * 4;

    const float* aptr = A + (size_t)(n0 + lr) * DMODEL + lk;
    const float* bptr = Bm + (size_t)(m0 + lr) * DMODEL + lk;

    uint64_t acc2[8][4];
#pragma unroll
    for (int i = 0; i < 8; i++)
#pragma unroll
        for (int j = 0; j < 4; j++) acc2[i][j] = 0ull;

    // prologue: tile 0 -> buf 0
    {
        float4 av = *(const float4*)(aptr);
        float4 bv = *(const float4*)(bptr);
        As[0][lk + 0][lr] = av.x; As[0][lk + 1][lr] = av.y;
        As[0][lk + 2][lr] = av.z; As[0][lk + 3][lr] = av.w;
        Bs[0][lk + 0][lr] = bv.x; Bs[0][lk + 1][lr] = bv.y;
        Bs[0][lk + 2][lr] = bv.z; Bs[0][lk + 3][lr] = bv.w;
    }
    __syncthreads();

    const int NT = DMODEL / BK;  // 32
    int cur = 0;
    for (int kt = 0; kt < NT; kt++) {
        float4 nav, nbv;
        if (kt + 1 < NT) {
            nav = *(const float4*)(aptr + (kt + 1) * BK);
            nbv = *(const float4*)(bptr + (kt + 1) * BK);
        }
#pragma unroll
        for (int kk = 0; kk < BK; kk++) {
            float4 a0 = *(const float4*)&As[cur][kk][ty * 8];
            float4 a1 = *(const float4*)&As[cur][kk][ty * 8 + 4];
            ulonglong2 bl0 = *(const ulonglong2*)&Bs[cur][kk][tx * 8];
            ulonglong2 bl1 = *(const ulonglong2*)&Bs[cur][kk][tx * 8 + 4];
            const uint64_t b2[4] = {bl0.x, bl0.y, bl1.x, bl1.y};
            const float a[8] = {a0.x, a0.y, a0.z, a0.w,
                                a1.x, a1.y, a1.z, a1.w};
#pragma unroll
            for (int i = 0; i < 8; i++) {
                const uint64_t aa = pack2(a[i], a[i]);
#pragma unroll
                for (int j = 0; j < 4; j++)
                    acc2[i][j] = ffma2(aa, b2[j], acc2[i][j]);
            }
        }
        __syncthreads();
        if (kt + 1 < NT) {
            const int nxt = cur ^ 1;
            As[nxt][lk + 0][lr] = nav.x; As[nxt][lk + 1][lr] = nav.y;
            As[nxt][lk + 2][lr] = nav.z; As[nxt][lk + 3][lr] = nav.w;
            Bs[nxt][lk + 0][lr] = nbv.x; Bs[nxt][lk + 1][lr] = nbv.y;
            Bs[nxt][lk + 2][lr] = nbv.z; Bs[nxt][lk + 3][lr] = nbv.w;
            __syncthreads();
            cur = nxt;
        }
    }

    const float scale = 0.0625f;  // exact 2^-4
#pragma unroll
    for (int i = 0; i < 8; i++) {
        const size_t rowoff = (size_t)(n0 + ty * 8 + i) * NC + m0 + tx * 8;
        float c0, c1, c2, c3, c4, c5, c6, c7;
        unpack2(acc2[i][0], c0, c1);
        unpack2(acc2[i][1], c2, c3);
        unpack2(acc2[i][2], c4, c5);
        unpack2(acc2[i][3], c6, c7);
        float4 o0, o1;
        o0.x = c0 * scale; o0.y = c1 * scale;
        o0.z = c2 * scale; o0.w = c3 * scale;
        o1.x = c4 * scale; o1.y = c5 * scale;
        o1.z = c6 * scale; o1.w = c7 * scale;
        *(float4*)(C + rowoff) = o0;
        *(float4*)(C + rowoff + 4) = o1;
    }
}

// ---------------- kernel 3: radix-select top-32 + softmax --------------------
__device__ __forceinline__ uint32_t fkey(float v) {
    uint32_t u = __float_as_uint(v);
    return (u & 0x80000000u) ? ~u : (u | 0x80000000u);
}
__device__ __forceinline__ float inv_key(uint32_t u) {
    return __uint_as_float((u & 0x80000000u) ? (u & 0x7FFFFFFFu) : ~u);
}
__device__ __forceinline__ void hist_add_full(int b, int* hist) {
    unsigned m = __match_any_sync(0xffffffffu, b);
    if ((threadIdx.x & 31) == (__ffs(m) - 1)) atomicAdd(&hist[b], __popc(m));
}

__global__ __launch_bounds__(256) void k_topk(float* __restrict__ out_attn,
                                              float* __restrict__ out_idxf)
{
    const int q = blockIdx.x;
    const float* __restrict__ row = g_scores + (size_t)q * NC;
    const int t = threadIdx.x;
    const int lane = t & 31, warp = t >> 5;

    __shared__ uint32_t s_keys[NC];    // 32 KB
    __shared__ int s_hist[256];
    __shared__ int s_S[257];
    __shared__ int s_info[4];
    __shared__ float s_candv[TOPK];
    __shared__ int   s_candi[TOPK];
    __shared__ int   s_cnt;
    __shared__ int   s_redi[8];
    __shared__ float s_topv[TOPK];
    __shared__ int   s_topi[TOPK];

    if (t < 256) s_hist[t] = 0;
    if (t == 0) { s_S[256] = 0; s_cnt = 0; }
    __syncthreads();

#pragma unroll
    for (int i = 0; i < 8; i++) {
        const int base = i * 1024 + (t << 2);
        float4 v4 = *(const float4*)(row + base);
        uint32_t u0 = fkey(v4.x), u1 = fkey(v4.y);
        uint32_t u2 = fkey(v4.z), u3 = fkey(v4.w);
        uint4 pk; pk.x = u0; pk.y = u1; pk.z = u2; pk.w = u3;
        *(uint4*)&s_keys[base] = pk;
        hist_add_full(u0 >> 24, s_hist);
        hist_add_full(u1 >> 24, s_hist);
        hist_add_full(u2 >> 24, s_hist);
        hist_add_full(u3 >> 24, s_hist);
    }

    int need = TOPK;
    uint32_t pref = 0;

    for (int p = 0; p < 4; p++) {
        __syncthreads();
        if (warp == 0) {
            const int base = lane * 8;
            int c[8];
#pragma unroll
            for (int k2 = 0; k2 < 8; k2++) c[k2] = s_hist[base + k2];
            int sum = 0;
#pragma unroll
            for (int k2 = 7; k2 >= 0; k2--) { sum += c[k2]; c[k2] = sum; }
            int v = sum;
#pragma unroll
            for (int off = 1; off < 32; off <<= 1) {
                int o = __shfl_down_sync(0xffffffffu, v, off);
                if (lane + off < 32) v += o;
            }
            const int run = v - sum;
#pragma unroll
            for (int k2 = 0; k2 < 8; k2++) s_S[base + k2] = c[k2] + run;
        }
        __syncthreads();
        if (t < 256) {
            if (s_S[t] >= need && s_S[t + 1] < need) {
                s_info[0] = t;
                s_info[1] = s_S[t + 1];
            }
        }
        __syncthreads();
        const int B = s_info[0];
        need -= s_info[1];
        pref = (pref << 8) | (uint32_t)B;

        if (p < 3) {
            if (t < 256) s_hist[t] = 0;
            __syncthreads();
            const int shift = 24 - 8 * (p + 1);
            for (int i = 0; i < 32; i++) {
                const uint32_t u = s_keys[i * 256 + t];
                if ((u >> (shift + 8)) == pref)
                    atomicAdd(&s_hist[(u >> shift) & 255], 1);
            }
        }
    }
    __syncthreads();

    const uint32_t T = pref;
    for (int i = 0; i < 32; i++) {
        const int idx = i * 256 + t;
        const uint32_t u = s_keys[idx];
        if (u > T) {
            const int pos = atomicAdd(&s_cnt, 1);
            s_candv[pos] = inv_key(u);
            s_candi[pos] = idx;
        }
    }
    __syncthreads();
    const int cab = s_cnt;
    const int r = TOPK - cab;

    int prev = -1;
    for (int j = 0; j < r; j++) {
        int mymin = 0x7fffffff;
        for (int i = 0; i < 32; i++) {
            const int idx = i * 256 + t;
            if (idx > prev && s_keys[idx] == T) { mymin = idx; break; }
        }
#pragma unroll
        for (int off = 16; off > 0; off >>= 1)
            mymin = min(mymin, __shfl_down_sync(0xffffffffu, mymin, off));
        if (lane == 0) s_redi[warp] = mymin;
        __syncthreads();
        if (t == 0) {
            int mn = s_redi[0];
#pragma unroll
            for (int w = 1; w < 8; w++) mn = min(mn, s_redi[w]);
            s_candi[cab + j] = mn;
            s_candv[cab + j] = inv_key(T);
            s_info[2] = mn;
        }
        __syncthreads();
        prev = s_info[2];
    }

    if (t < TOPK) {
        const float mv = s_candv[t];
        const int mi = s_candi[t];
        int rank = 0;
#pragma unroll
        for (int j = 0; j < TOPK; j++) {
            const float ov = s_candv[j];
            const int oi = s_candi[j];
            rank += (ov > mv) || (ov == mv && oi < mi);
        }
        s_topv[rank] = mv;
        s_topi[rank] = mi;
    }
    __syncthreads();

    if (warp == 0) {
        const float val = s_topv[lane];
        float m = val;
#pragma unroll
        for (int s = 16; s > 0; s >>= 1)
            m = fmaxf(m, __shfl_xor_sync(0xffffffffu, m, s));
        const float e = expf(val - m);
        float sum = e;
#pragma unroll
        for (int s = 16; s > 0; s >>= 1)
            sum += __shfl_xor_sync(0xffffffffu, sum, s);
        const float a = e / sum;
        out_attn[(size_t)q * TOPK + lane] = a;
        out_idxf[(size_t)q * TOPK + lane] = (float)s_topi[lane];
        g_attn[(size_t)q * TOPK + lane] = a;
        g_idx[(size_t)q * TOPK + lane] = s_topi[lane];
    }
}

// ---------------- kernel 4: context gather + out proj + residual -------------
__global__ __launch_bounds__(256) void k_final(const float* __restrict__ op_w,
                                               const float* __restrict__ op_b,
                                               float* __restrict__ out)
{
    const int QB = 8;
    __shared__ float s_attn[QB][TOPK];
    __shared__ int s_idx2[QB][TOPK];
    __shared__ float s_ctx[QB][DMODEL];
    const int t = threadIdx.x;
    const int q0 = blockIdx.x * QB;
    const int b = q0 / ND;

    if (t < QB * TOPK) {
        s_attn[t / TOPK][t & 31] = g_attn[(size_t)q0 * TOPK + t];
        s_idx2[t / TOPK][t & 31] = g_idx[(size_t)q0 * TOPK + t];
    }
    __syncthreads();

    const float* __restrict__ V = g_Vf + (size_t)b * NC * DMODEL;
#pragma unroll
    for (int r = 0; r < QB; r++) {
        float c = 0.f;
#pragma unroll 8
        for (int k = 0; k < TOPK; k++)
            c = fmaf(s_attn[r][k], V[(size_t)s_idx2[r][k] * DMODEL + t], c);
        s_ctx[r][t] = c;
    }
    __syncthreads();

    float o[QB];
    const float bias = op_b[t];
#pragma unroll
    for (int r = 0; r < QB; r++) o[r] = 0.f;

    for (int d = 0; d < DMODEL; d += 2) {
        const float w0 = op_w[(size_t)d * DMODEL + t];
        const float w1 = op_w[(size_t)(d + 1) * DMODEL + t];
#pragma unroll
        for (int r = 0; r < QB; r++) {
            float2 c2 = *(const float2*)&s_ctx[r][d];
            o[r] = fmaf(c2.y, w1, fmaf(c2.x, w0, o[r]));
        }
    }
#pragma unroll
    for (int r = 0; r < QB; r++)
        out[(size_t)(q0 + r) * DMODEL + t] =
            g_xmicro[(size_t)(q0 + r) * DMODEL + t] + o[r] + bias;
}

// ---------------- launch -----------------------------------------------------
extern "C" void kernel_launch(void* const* d_in, const int* in_sizes, int n_in,
                              void* d_out, int out_size)
{
    const float* micro = (const float*)d_in[0];
    const float* macro = (const float*)d_in[1];
    const float* mp_w = (const float*)d_in[2];
    const float* mp_b = (const float*)d_in[3];
    const float* wq = (const float*)d_in[4];
    const float* wk = (const float*)d_in[5];
    const float* wv = (const float*)d_in[6];
    const float* op_w = (const float*)d_in[7];
    const float* op_b = (const float*)d_in[8];

    float* out = (float*)d_out;
    float* out_attn = out + (size_t)BSZ * ND * DMODEL;
    float* out_idxf = out_attn + (size_t)BSZ * ND * TOPK;

    k_proj_q<<<(BSZ * ND) / 32, 256>>>(micro, mp_w, mp_b, wq);
    k_proj_kv<<<(BSZ * NC) / 32, 256>>>(macro, wk, wv);
    dim3 g2(NC / BN, ND / BM, BSZ);
    k_scores<<<g2, 256>>>();
    k_topk<<<BSZ * ND, 256>>>(out_attn, out_idxf);
    k_final<<<(BSZ * ND) / 8, 256>>>(op_w, op_b, out);
}

// round 7
// speedup vs baseline: 1.9720x; 1.2821x over previous
#include <cuda_runtime.h>
#include <cuda_bf16.h>
#include <float.h>
#include <math.h>
#include <stdint.h>

#define BSZ 4
#define ND 2048
#define NC 8192
#define DM 11
#define DMODEL 256
#define TOPK 32
#define NCAND 64

// ---------------- scratch (no allocations allowed) ----------------
__device__ float g_xmicro[BSZ * ND * DMODEL];
__device__ float g_Q[BSZ * ND * DMODEL];
__device__ float g_Kf[BSZ * NC * DMODEL];
__device__ float g_Vf[BSZ * NC * DMODEL];
__device__ float g_scores[(size_t)BSZ * ND * NC];      // approx scores
__device__ __nv_bfloat16 g_Q1[BSZ * ND * DMODEL];
__device__ __nv_bfloat16 g_Q2[BSZ * ND * DMODEL];
__device__ __nv_bfloat16 g_K1[BSZ * NC * DMODEL];
__device__ __nv_bfloat16 g_K2[BSZ * NC * DMODEL];
__device__ int   g_candi[BSZ * ND * NCAND];
__device__ float g_attn[BSZ * ND * TOPK];
__device__ int   g_idx[BSZ * ND * TOPK];

// ---------------- packed f32x2 helpers ---------------------------------------
__device__ __forceinline__ uint64_t pack2(float lo, float hi) {
    uint64_t d;
    asm("mov.b64 %0, {%1, %2};" : "=l"(d) : "f"(lo), "f"(hi));
    return d;
}
__device__ __forceinline__ void unpack2(uint64_t v, float& lo, float& hi) {
    asm("mov.b64 {%0, %1}, %2;" : "=f"(lo), "=f"(hi) : "l"(v));
}
__device__ __forceinline__ uint64_t ffma2(uint64_t a, uint64_t b, uint64_t c) {
    uint64_t d;
    asm("fma.rn.f32x2 %0, %1, %2, %3;" : "=l"(d) : "l"(a), "l"(b), "l"(c));
    return d;
}

// ---------------- mma.sync helpers (portable sm_80+ path) --------------------
__device__ __forceinline__ uint32_t smem_u32(const void* p) {
    uint32_t a;
    asm("{ .reg .u64 t; cvta.to.shared.u64 t, %1; cvt.u32.u64 %0, t; }"
        : "=r"(a) : "l"(p));
    return a;
}
__device__ __forceinline__ void ldsm4(uint32_t& r0, uint32_t& r1, uint32_t& r2,
                                      uint32_t& r3, uint32_t addr) {
    asm volatile("ldmatrix.sync.aligned.m8n8.x4.shared.b16 {%0,%1,%2,%3}, [%4];"
                 : "=r"(r0), "=r"(r1), "=r"(r2), "=r"(r3) : "r"(addr));
}
__device__ __forceinline__ void mma16816(float& d0, float& d1, float& d2,
                                         float& d3, uint32_t a0, uint32_t a1,
                                         uint32_t a2, uint32_t a3, uint32_t b0,
                                         uint32_t b1) {
    asm volatile(
        "mma.sync.aligned.m16n8k16.row.col.f32.bf16.bf16.f32 "
        "{%0,%1,%2,%3}, {%4,%5,%6,%7}, {%8,%9}, {%0,%1,%2,%3};"
        : "+f"(d0), "+f"(d1), "+f"(d2), "+f"(d3)
        : "r"(a0), "r"(a1), "r"(a2), "r"(a3), "r"(b0), "r"(b1));
}

// ---------------- kernel 0: x_micro ; Q (+bf16 splits) ----------------------
__global__ __launch_bounds__(256) void k_proj_q(
    const float* __restrict__ micro, const float* __restrict__ mp_w,
    const float* __restrict__ mp_b, const float* __restrict__ wq)
{
    const int RB = 32;
    __shared__ float s_micro[RB][DM];
    __shared__ float s_mpw[DM][DMODEL];
    __shared__ float s_x[RB][DMODEL];
    const int t = threadIdx.x;
    const int row0 = blockIdx.x * RB;

    for (int i = t; i < RB * DM; i += 256)
        s_micro[i / DM][i % DM] = micro[(size_t)row0 * DM + i];
    for (int i = t; i < DM * DMODEL; i += 256)
        s_mpw[i / DMODEL][i % DMODEL] = mp_w[i];
    __syncthreads();

    const float bias = mp_b[t];
    for (int r = 0; r < RB; r++) {
        float acc = 0.f;
#pragma unroll
        for (int i = 0; i < DM; i++)
            acc = fmaf(s_micro[r][i], s_mpw[i][t], acc);
        acc = acc + bias;
        s_x[r][t] = acc;
        g_xmicro[(size_t)(row0 + r) * DMODEL + t] = acc;
    }
    __syncthreads();

    float q[RB];
#pragma unroll
    for (int r = 0; r < RB; r++) q[r] = 0.f;
    for (int d = 0; d < DMODEL; d += 2) {
        const float w0 = wq[(size_t)d * DMODEL + t];
        const float w1 = wq[(size_t)(d + 1) * DMODEL + t];
#pragma unroll
        for (int r = 0; r < RB; r++) {
            float2 x2 = *(const float2*)&s_x[r][d];
            q[r] = fmaf(x2.y, w1, fmaf(x2.x, w0, q[r]));
        }
    }
    for (int r = 0; r < RB; r++) {
        const float v = q[r];
        const size_t o = (size_t)(row0 + r) * DMODEL + t;
        g_Q[o] = v;
        __nv_bfloat16 h1 = __float2bfloat16(v);
        g_Q1[o] = h1;
        g_Q2[o] = __float2bfloat16(v - __bfloat162float(h1));
    }
}

// ---------------- kernel 1: K_full, V_full (+bf16 splits of K) ---------------
__global__ __launch_bounds__(256) void k_proj_kv(
    const float* __restrict__ macro, const float* __restrict__ wk,
    const float* __restrict__ wv)
{
    const int RB = 32;
    __shared__ float s_x[DMODEL][RB + 2];
    const int t = threadIdx.x;
    const int row0 = blockIdx.x * RB;

#pragma unroll 4
    for (int r = 0; r < RB; r++)
        s_x[t][r] = macro[(size_t)(row0 + r) * DMODEL + t];
    __syncthreads();

    uint64_t ka2[RB / 2], va2[RB / 2];
#pragma unroll
    for (int p = 0; p < RB / 2; p++) { ka2[p] = 0ull; va2[p] = 0ull; }

    for (int d = 0; d < DMODEL; d++) {
        const float kw = wk[(size_t)d * DMODEL + t];
        const float vw = wv[(size_t)d * DMODEL + t];
        const uint64_t kw2 = pack2(kw, kw);
        const uint64_t vw2 = pack2(vw, vw);
#pragma unroll
        for (int p = 0; p < RB / 2; p++) {
            const uint64_t x2 = *(const uint64_t*)&s_x[d][2 * p];
            ka2[p] = ffma2(x2, kw2, ka2[p]);
            va2[p] = ffma2(x2, vw2, va2[p]);
        }
    }
#pragma unroll
    for (int p = 0; p < RB / 2; p++) {
        float k0, k1, v0, v1;
        unpack2(ka2[p], k0, k1);
        unpack2(va2[p], v0, v1);
        const size_t o0 = (size_t)(row0 + 2 * p) * DMODEL + t;
        const size_t o1 = o0 + DMODEL;
        g_Kf[o0] = k0; g_Kf[o1] = k1;
        g_Vf[o0] = v0; g_Vf[o1] = v1;
        __nv_bfloat16 h0 = __float2bfloat16(k0);
        __nv_bfloat16 h1 = __float2bfloat16(k1);
        g_K1[o0] = h0; g_K1[o1] = h1;
        g_K2[o0] = __float2bfloat16(k0 - __bfloat162float(h0));
        g_K2[o1] = __float2bfloat16(k1 - __bfloat162float(h1));
    }
}

// ---------------- kernel 2: approx scores via bf16 split mma.sync -----------
// C[q,c] ~= (q1k1 + q1k2 + q2k1) * 2^-4, fp32 accum. 128x128 tile / CTA,
// 8 warps x (64x32). K-tile 32, padded smem stride 40 bf16 (LDSM conflict-free).
#define KT 32
#define SSTR 40
__global__ __launch_bounds__(256) void k_mma_scores()
{
    __shared__ __align__(16) __nv_bfloat16 sA1[128 * SSTR];
    __shared__ __align__(16) __nv_bfloat16 sA2[128 * SSTR];
    __shared__ __align__(16) __nv_bfloat16 sB1[128 * SSTR];
    __shared__ __align__(16) __nv_bfloat16 sB2[128 * SSTR];

    const int t = threadIdx.x;
    const int lane = t & 31, warp = t >> 5;
    const int b = blockIdx.z;
    const int q0 = blockIdx.y * 128;   // query rows
    const int c0 = blockIdx.x * 128;   // cell rows

    const __nv_bfloat16* Q1 = g_Q1 + (size_t)b * ND * DMODEL;
    const __nv_bfloat16* Q2 = g_Q2 + (size_t)b * ND * DMODEL;
    const __nv_bfloat16* K1 = g_K1 + (size_t)b * NC * DMODEL;
    const __nv_bfloat16* K2 = g_K2 + (size_t)b * NC * DMODEL;

    const int wq0 = (warp & 1) * 64;   // warp m-offset (queries)
    const int wc0 = (warp >> 1) * 32;  // warp n-offset (cells)

    float acc[4][4][4];
#pragma unroll
    for (int i = 0; i < 4; i++)
#pragma unroll
        for (int j = 0; j < 4; j++)
#pragma unroll
            for (int k = 0; k < 4; k++) acc[i][j][k] = 0.f;

    // ldmatrix lane address components
    const uint32_t a1base = smem_u32(sA1), a2base = smem_u32(sA2);
    const uint32_t b1base = smem_u32(sB1), b2base = smem_u32(sB2);
    const int arow = lane & 15, ak8 = (lane >> 4) * 8;
    const int brow = ((lane >> 3) & 1) * 8 + (lane & 7), bk8 = (lane >> 4) * 8;

    for (int kt = 0; kt < DMODEL / KT; kt++) {
        // load k-tile: each thread 2 x uint4 (8 bf16) per array
#pragma unroll
        for (int i = 0; i < 2; i++) {
            const int idx = t + i * 256;
            const int r = idx >> 2;
            const int c8 = (idx & 3) * 8;
            const size_t goff = (size_t)r * DMODEL + kt * KT + c8;
            const int soff = r * SSTR + c8;
            *(uint4*)&sA1[soff] = *(const uint4*)(Q1 + (size_t)q0 * DMODEL + goff);
            *(uint4*)&sA2[soff] = *(const uint4*)(Q2 + (size_t)q0 * DMODEL + goff);
            *(uint4*)&sB1[soff] = *(const uint4*)(K1 + (size_t)c0 * DMODEL + goff);
            *(uint4*)&sB2[soff] = *(const uint4*)(K2 + (size_t)c0 * DMODEL + goff);
        }
        __syncthreads();

#pragma unroll
        for (int ks = 0; ks < 2; ks++) {
            const int k0 = ks * 16;
            uint32_t a1[4][4], a2[4][4], b1[4][2], b2[4][2];
#pragma unroll
            for (int mt = 0; mt < 4; mt++) {
                const uint32_t off =
                    ((wq0 + mt * 16 + arow) * SSTR + k0 + ak8) * 2;
                ldsm4(a1[mt][0], a1[mt][1], a1[mt][2], a1[mt][3], a1base + off);
                ldsm4(a2[mt][0], a2[mt][1], a2[mt][2], a2[mt][3], a2base + off);
            }
#pragma unroll
            for (int nh = 0; nh < 2; nh++) {  // two n16 halves -> 4 n8 tiles
                const uint32_t off =
                    ((wc0 + nh * 16 + brow) * SSTR + k0 + bk8) * 2;
                uint32_t r0, r1, r2, r3;
                ldsm4(r0, r1, r2, r3, b1base + off);
                b1[nh * 2 + 0][0] = r0; b1[nh * 2 + 0][1] = r2;
                b1[nh * 2 + 1][0] = r1; b1[nh * 2 + 1][1] = r3;
                ldsm4(r0, r1, r2, r3, b2base + off);
                b2[nh * 2 + 0][0] = r0; b2[nh * 2 + 0][1] = r2;
                b2[nh * 2 + 1][0] = r1; b2[nh * 2 + 1][1] = r3;
            }
#pragma unroll
            for (int mt = 0; mt < 4; mt++)
#pragma unroll
                for (int nt = 0; nt < 4; nt++) {
                    float* d = acc[mt][nt];
                    mma16816(d[0], d[1], d[2], d[3], a1[mt][0], a1[mt][1],
                             a1[mt][2], a1[mt][3], b1[nt][0], b1[nt][1]);
                    mma16816(d[0], d[1], d[2], d[3], a1[mt][0], a1[mt][1],
                             a1[mt][2], a1[mt][3], b2[nt][0], b2[nt][1]);
                    mma16816(d[0], d[1], d[2], d[3], a2[mt][0], a2[mt][1],
                             a2[mt][2], a2[mt][3], b1[nt][0], b1[nt][1]);
                }
        }
        __syncthreads();
    }

    // epilogue
    const int g = lane >> 2, tg = lane & 3;
    float* __restrict__ C = g_scores + (size_t)b * ND * NC;
#pragma unroll
    for (int mt = 0; mt < 4; mt++) {
#pragma unroll
        for (int nt = 0; nt < 4; nt++) {
            const float* d = acc[mt][nt];
            const int qrow = q0 + wq0 + mt * 16 + g;
            const int col = c0 + wc0 + nt * 8 + tg * 2;
            float2 lo, hi;
            lo.x = d[0] * 0.0625f; lo.y = d[1] * 0.0625f;
            hi.x = d[2] * 0.0625f; hi.y = d[3] * 0.0625f;
            *(float2*)(C + (size_t)qrow * NC + col) = lo;
            *(float2*)(C + (size_t)(qrow + 8) * NC + col) = hi;
        }
    }
}

// ---------------- kernel 3: radix-select top-64 candidate indices -----------
__device__ __forceinline__ uint32_t fkey(float v) {
    uint32_t u = __float_as_uint(v);
    return (u & 0x80000000u) ? ~u : (u | 0x80000000u);
}
__device__ __forceinline__ void hist_add_full(int b, int* hist) {
    unsigned m = __match_any_sync(0xffffffffu, b);
    if ((threadIdx.x & 31) == (__ffs(m) - 1)) atomicAdd(&hist[b], __popc(m));
}

__global__ __launch_bounds__(256) void k_cand()
{
    const int q = blockIdx.x;
    const float* __restrict__ row = g_scores + (size_t)q * NC;
    const int t = threadIdx.x;
    const int lane = t & 31, warp = t >> 5;

    __shared__ uint32_t s_keys[NC];
    __shared__ int s_hist[256];
    __shared__ int s_S[257];
    __shared__ int s_info[4];
    __shared__ int s_candi[NCAND];
    __shared__ int s_cnt;
    __shared__ int s_redi[8];

    if (t < 256) s_hist[t] = 0;
    if (t == 0) { s_S[256] = 0; s_cnt = 0; }
    __syncthreads();

#pragma unroll
    for (int i = 0; i < 8; i++) {
        const int base = i * 1024 + (t << 2);
        float4 v4 = *(const float4*)(row + base);
        uint32_t u0 = fkey(v4.x), u1 = fkey(v4.y);
        uint32_t u2 = fkey(v4.z), u3 = fkey(v4.w);
        uint4 pk; pk.x = u0; pk.y = u1; pk.z = u2; pk.w = u3;
        *(uint4*)&s_keys[base] = pk;
        hist_add_full(u0 >> 24, s_hist);
        hist_add_full(u1 >> 24, s_hist);
        hist_add_full(u2 >> 24, s_hist);
        hist_add_full(u3 >> 24, s_hist);
    }

    int need = NCAND;
    uint32_t pref = 0;

    for (int p = 0; p < 4; p++) {
        __syncthreads();
        if (warp == 0) {
            const int base = lane * 8;
            int c[8];
#pragma unroll
            for (int k2 = 0; k2 < 8; k2++) c[k2] = s_hist[base + k2];
            int sum = 0;
#pragma unroll
            for (int k2 = 7; k2 >= 0; k2--) { sum += c[k2]; c[k2] = sum; }
            int v = sum;
#pragma unroll
            for (int off = 1; off < 32; off <<= 1) {
                int o = __shfl_down_sync(0xffffffffu, v, off);
                if (lane + off < 32) v += o;
            }
            const int run = v - sum;
#pragma unroll
            for (int k2 = 0; k2 < 8; k2++) s_S[base + k2] = c[k2] + run;
        }
        __syncthreads();
        if (t < 256) {
            if (s_S[t] >= need && s_S[t + 1] < need) {
                s_info[0] = t;
                s_info[1] = s_S[t + 1];
            }
        }
        __syncthreads();
        const int B = s_info[0];
        need -= s_info[1];
        pref = (pref << 8) | (uint32_t)B;

        if (p < 3) {
            if (t < 256) s_hist[t] = 0;
            __syncthreads();
            const int shift = 24 - 8 * (p + 1);
            for (int i = 0; i < 32; i++) {
                const uint32_t u = s_keys[i * 256 + t];
                if ((u >> (shift + 8)) == pref)
                    atomicAdd(&s_hist[(u >> shift) & 255], 1);
            }
        }
    }
    __syncthreads();

    const uint32_t T = pref;
    for (int i = 0; i < 32; i++) {
        const int idx = i * 256 + t;
        if (s_keys[idx] > T) {
            const int pos = atomicAdd(&s_cnt, 1);
            s_candi[pos] = idx;
        }
    }
    __syncthreads();
    const int cab = s_cnt;
    const int r = NCAND - cab;

    int prev = -1;
    for (int j = 0; j < r; j++) {
        int mymin = 0x7fffffff;
        for (int i = 0; i < 32; i++) {
            const int idx = i * 256 + t;
            if (idx > prev && s_keys[idx] == T) { mymin = idx; break; }
        }
#pragma unroll
        for (int off = 16; off > 0; off >>= 1)
            mymin = min(mymin, __shfl_down_sync(0xffffffffu, mymin, off));
        if (lane == 0) s_redi[warp] = mymin;
        __syncthreads();
        if (t == 0) {
            int mn = s_redi[0];
#pragma unroll
            for (int w = 1; w < 8; w++) mn = min(mn, s_redi[w]);
            s_candi[cab + j] = mn;
            s_info[2] = mn;
        }
        __syncthreads();
        prev = s_info[2];
    }

    if (t < NCAND) g_candi[(size_t)q * NCAND + t] = s_candi[t];
}

// ---------------- kernel 4: exact refine + top-32 + softmax ------------------
// Reference-bit-exact fp32 chain: acc=0; ascending d: fmaf; *0.0625f.
__global__ __launch_bounds__(64) void k_refine(float* __restrict__ out_attn,
                                               float* __restrict__ out_idxf)
{
    const int q = blockIdx.x;
    const int b = q / ND;
    const int t = threadIdx.x;

    __shared__ float s_q[DMODEL];
    __shared__ float s_v[NCAND];
    __shared__ int   s_i[NCAND];
    __shared__ float s_topv[TOPK];
    __shared__ int   s_topi[TOPK];

    *(float4*)&s_q[t * 4] = *(const float4*)(g_Q + (size_t)q * DMODEL + t * 4);
    __syncthreads();

    const int ci = g_candi[(size_t)q * NCAND + t];
    const float* __restrict__ kr = g_Kf + ((size_t)b * NC + ci) * DMODEL;
    float acc = 0.f;
#pragma unroll 16
    for (int d4 = 0; d4 < DMODEL / 4; d4++) {
        const float4 kv = __ldg((const float4*)(kr + d4 * 4));
        acc = fmaf(s_q[d4 * 4 + 0], kv.x, acc);
        acc = fmaf(s_q[d4 * 4 + 1], kv.y, acc);
        acc = fmaf(s_q[d4 * 4 + 2], kv.z, acc);
        acc = fmaf(s_q[d4 * 4 + 3], kv.w, acc);
    }
    const float val = acc * 0.0625f;
    s_v[t] = val;
    s_i[t] = ci;
    __syncthreads();

    int rank = 0;
#pragma unroll
    for (int j = 0; j < NCAND; j++) {
        const float ov = s_v[j];
        const int oi = s_i[j];
        rank += (ov > val) || (ov == val && oi < ci);
    }
    if (rank < TOPK) { s_topv[rank] = val; s_topi[rank] = ci; }
    __syncthreads();

    if (t < TOPK) {
        const float v = s_topv[t];
        float m = v;
#pragma unroll
        for (int s = 16; s > 0; s >>= 1)
            m = fmaxf(m, __shfl_xor_sync(0xffffffffu, m, s));
        const float e = expf(v - m);
        float sum = e;
#pragma unroll
        for (int s = 16; s > 0; s >>= 1)
            sum += __shfl_xor_sync(0xffffffffu, sum, s);
        const float a = e / sum;
        out_attn[(size_t)q * TOPK + t] = a;
        out_idxf[(size_t)q * TOPK + t] = (float)s_topi[t];
        g_attn[(size_t)q * TOPK + t] = a;
        g_idx[(size_t)q * TOPK + t] = s_topi[t];
    }
}

// ---------------- kernel 5: context gather + out proj + residual -------------
__global__ __launch_bounds__(256) void k_final(const float* __restrict__ op_w,
                                               const float* __restrict__ op_b,
                                               float* __restrict__ out)
{
    const int QB = 8;
    __shared__ float s_attn[QB][TOPK];
    __shared__ int s_idx2[QB][TOPK];
    __shared__ float s_ctx[QB][DMODEL];
    const int t = threadIdx.x;
    const int q0 = blockIdx.x * QB;
    const int b = q0 / ND;

    if (t < QB * TOPK) {
        s_attn[t / TOPK][t & 31] = g_attn[(size_t)q0 * TOPK + t];
        s_idx2[t / TOPK][t & 31] = g_idx[(size_t)q0 * TOPK + t];
    }
    __syncthreads();

    const float* __restrict__ V = g_Vf + (size_t)b * NC * DMODEL;
#pragma unroll
    for (int r = 0; r < QB; r++) {
        float c = 0.f;
#pragma unroll 8
        for (int k = 0; k < TOPK; k++)
            c = fmaf(s_attn[r][k], V[(size_t)s_idx2[r][k] * DMODEL + t], c);
        s_ctx[r][t] = c;
    }
    __syncthreads();

    float o[QB];
    const float bias = op_b[t];
#pragma unroll
    for (int r = 0; r < QB; r++) o[r] = 0.f;

    for (int d = 0; d < DMODEL; d += 2) {
        const float w0 = op_w[(size_t)d * DMODEL + t];
        const float w1 = op_w[(size_t)(d + 1) * DMODEL + t];
#pragma unroll
        for (int r = 0; r < QB; r++) {
            float2 c2 = *(const float2*)&s_ctx[r][d];
            o[r] = fmaf(c2.y, w1, fmaf(c2.x, w0, o[r]));
        }
    }
#pragma unroll
    for (int r = 0; r < QB; r++)
        out[(size_t)(q0 + r) * DMODEL + t] =
            g_xmicro[(size_t)(q0 + r) * DMODEL + t] + o[r] + bias;
}

// ---------------- launch -----------------------------------------------------
extern "C" void kernel_launch(void* const* d_in, const int* in_sizes, int n_in,
                              void* d_out, int out_size)
{
    const float* micro = (const float*)d_in[0];
    const float* macro = (const float*)d_in[1];
    const float* mp_w = (const float*)d_in[2];
    const float* mp_b = (const float*)d_in[3];
    const float* wq = (const float*)d_in[4];
    const float* wk = (const float*)d_in[5];
    const float* wv = (const float*)d_in[6];
    const float* op_w = (const float*)d_in[7];
    const float* op_b = (const float*)d_in[8];

    float* out = (float*)d_out;
    float* out_attn = out + (size_t)BSZ * ND * DMODEL;
    float* out_idxf = out_attn + (size_t)BSZ * ND * TOPK;

    k_proj_q<<<(BSZ * ND) / 32, 256>>>(micro, mp_w, mp_b, wq);
    k_proj_kv<<<(BSZ * NC) / 32, 256>>>(macro, wk, wv);
    dim3 gm(NC / 128, ND / 128, BSZ);
    k_mma_scores<<<gm, 256>>>();
    k_cand<<<BSZ * ND, 256>>>();
    k_refine<<<BSZ * ND, 64>>>(out_attn, out_idxf);
    k_final<<<(BSZ * ND) / 8, 256>>>(op_w, op_b, out);
}